// round 1
// baseline (speedup 1.0000x reference)
#include <cuda_runtime.h>

#define Bc 8
#define Pc 512
#define Dc 16
#define Ec 64
#define Hc 128

// Scratch (no allocations allowed -> __device__ globals)
__device__ float g_a[Bc * Pc * Hc];     // a_s = ns @ We1[17:33]          (2 MB)
__device__ float g_c[Bc * Pc * Hc];     // c_r = nr @ We1[1:17] + be1     (2 MB)
__device__ float g_dist[Bc * Pc * Pc];  // dist[b][r][s]                  (8 MB)
__device__ float g_hsum[Bc * Pc * Hc];  // sum_s relu(hidden)             (2 MB)

// ---------------------------------------------------------------------------
// K1: per-node precompute a, c.  8 nodes per block, 128 threads (thread = k).
// ---------------------------------------------------------------------------
__global__ void pre_kernel(const float* __restrict__ h,
                           const float* __restrict__ We1,
                           const float* __restrict__ be1) {
    int node0 = blockIdx.x * 8;  // global node index b*512+p
    int k = threadIdx.x;

    __shared__ float nd[8][Dc];
    // 8*16 = 128 values, one per thread
    nd[k >> 4][k & 15] = h[node0 * Dc + k];
    __syncthreads();

    float a[8], c[8];
    float b1 = be1[k];
#pragma unroll
    for (int n = 0; n < 8; n++) { a[n] = 0.f; c[n] = b1; }

#pragma unroll
    for (int d = 0; d < Dc; d++) {
        float ws = We1[(17 + d) * Hc + k];  // sender rows
        float wr = We1[(1 + d) * Hc + k];   // receiver rows
#pragma unroll
        for (int n = 0; n < 8; n++) {
            float x = nd[n][d];
            a[n] = fmaf(x, ws, a[n]);
            c[n] = fmaf(x, wr, c[n]);
        }
    }
#pragma unroll
    for (int n = 0; n < 8; n++) {
        g_a[(node0 + n) * Hc + k] = a[n];
        g_c[(node0 + n) * Hc + k] = c[n];
    }
}

// ---------------------------------------------------------------------------
// K2: pairwise distance matrix dist[b][r][s].
// Block = (batch, 16-receiver chunk). Full node batch staged in padded smem.
// ---------------------------------------------------------------------------
__global__ void dist_kernel(const float* __restrict__ h) {
    int b = blockIdx.x >> 5;        // /32
    int rc = blockIdx.x & 31;       // 16 receivers per chunk
    __shared__ float nd[Pc][Dc + 1];  // pad to kill 16-way bank conflicts

    for (int i = threadIdx.x; i < Pc * Dc; i += blockDim.x)
        nd[i >> 4][i & 15] = h[b * Pc * Dc + i];
    __syncthreads();

    for (int idx = threadIdx.x; idx < 16 * Pc; idx += blockDim.x) {
        int r = rc * 16 + (idx >> 9);
        int s = idx & (Pc - 1);
        float acc = 0.f;
#pragma unroll
        for (int d = 0; d < Dc; d++) {
            float df = nd[r][d] - nd[s][d];
            acc = fmaf(df, df, acc);
        }
        g_dist[(b * Pc + r) * Pc + s] = sqrtf(acc);
    }
}

// ---------------------------------------------------------------------------
// K3: edge accumulation.  hsum[r][k] = sum_{s != r} relu(dist*w0[k]+a_s[k]+c_r[k])
// Block = (batch, 8 receivers), 128 threads (thread = hidden unit k).
// dist tile staged in smem (pure broadcast reads); a streamed from L2.
// s == r term removed exactly at the end (dist(r,r) == 0 exactly).
// ---------------------------------------------------------------------------
__global__ void edge_kernel(const float* __restrict__ We1) {
    int b = blockIdx.x >> 6;             // /64
    int r0 = (blockIdx.x & 63) * 8;
    int k = threadIdx.x;

    float w0 = We1[k];  // row 0 = dist weight
    float cr[8], acc[8];
#pragma unroll
    for (int n = 0; n < 8; n++) {
        cr[n] = g_c[(b * Pc + r0 + n) * Hc + k];
        acc[n] = 0.f;
    }

    __shared__ float sd[8][64];
    const float* arow = g_a + b * Pc * Hc;
    const float* drow = g_dist + (size_t)(b * Pc + r0) * Pc;

    for (int st = 0; st < Pc; st += 64) {
        __syncthreads();
        // stage dist tile: 8 receivers x 64 senders
#pragma unroll
        for (int i = 0; i < 4; i++) {
            int idx = threadIdx.x + i * 128;
            sd[idx >> 6][idx & 63] = drow[(idx >> 6) * Pc + st + (idx & 63)];
        }
        __syncthreads();

#pragma unroll 4
        for (int ss = 0; ss < 64; ss++) {
            float av = arow[(st + ss) * Hc + k];
#pragma unroll
            for (int n = 0; n < 8; n++) {
                float pre = fmaf(sd[n][ss], w0, av + cr[n]);
                acc[n] += fmaxf(pre, 0.f);
            }
        }
    }

#pragma unroll
    for (int n = 0; n < 8; n++) {
        // remove the s == r contribution: dist = 0 -> relu(a_r + c_r), exact
        float ar = arow[(r0 + n) * Hc + k];
        acc[n] -= fmaxf(ar + cr[n], 0.f);
        g_hsum[(b * Pc + r0 + n) * Hc + k] = acc[n];
    }
}

// ---------------------------------------------------------------------------
// K4: agg = hsum @ We2 + 511*be2 ; node MLP.  8 nodes per block, 128 threads.
// ---------------------------------------------------------------------------
__global__ void post_kernel(const float* __restrict__ h,
                            const float* __restrict__ We2,
                            const float* __restrict__ be2,
                            const float* __restrict__ Wn1,
                            const float* __restrict__ bn1,
                            const float* __restrict__ Wn2,
                            const float* __restrict__ bn2,
                            float* __restrict__ out) {
    int node0 = blockIdx.x * 8;
    int t = threadIdx.x;

    __shared__ float Hs[8][Hc];
    __shared__ float nin[8][Ec + Dc];  // [agg(64) | node(16)]
    __shared__ float hid[8][Hc];

    for (int i = t; i < 8 * Hc; i += 128)
        Hs[i >> 7][i & (Hc - 1)] = g_hsum[node0 * Hc + i];
    // node features into nin[:, 64:80]
    nin[t >> 4][Ec + (t & 15)] = h[node0 * Dc + t];
    __syncthreads();

    // agg: 8 nodes x 64 outputs = 512; each thread does 4
    {
        int j = t & 63;
        int nb = t >> 6;  // 0 or 1
        float b2 = 511.0f * be2[j];
#pragma unroll
        for (int it = 0; it < 4; it++) {
            int n = nb + it * 2;
            float acc = b2;
#pragma unroll 8
            for (int kk = 0; kk < Hc; kk++)
                acc = fmaf(Hs[n][kk], We2[kk * Ec + j], acc);
            nin[n][j] = acc;
        }
    }
    __syncthreads();

    // hidden layer: thread t = hidden unit, 8 nodes in registers
    {
        float accs[8];
        float b1 = bn1[t];
#pragma unroll
        for (int n = 0; n < 8; n++) accs[n] = b1;
#pragma unroll 8
        for (int i = 0; i < Ec + Dc; i++) {
            float w = Wn1[i * Hc + t];
#pragma unroll
            for (int n = 0; n < 8; n++)
                accs[n] = fmaf(nin[n][i], w, accs[n]);
        }
#pragma unroll
        for (int n = 0; n < 8; n++)
            hid[n][t] = fmaxf(accs[n], 0.f);
    }
    __syncthreads();

    // output layer: 8 nodes x 16 dims = 128 outputs, one per thread
    {
        int n = t >> 4, d = t & 15;
        float acc = bn2[d];
#pragma unroll 8
        for (int kk = 0; kk < Hc; kk++)
            acc = fmaf(hid[n][kk], Wn2[kk * Dc + d], acc);
        out[node0 * Dc + t] = acc;
    }
}

// ---------------------------------------------------------------------------
extern "C" void kernel_launch(void* const* d_in, const int* in_sizes, int n_in,
                              void* d_out, int out_size) {
    const float* h   = (const float*)d_in[0];
    const float* We1 = (const float*)d_in[1];
    const float* be1 = (const float*)d_in[2];
    const float* We2 = (const float*)d_in[3];
    const float* be2 = (const float*)d_in[4];
    const float* Wn1 = (const float*)d_in[5];
    const float* bn1 = (const float*)d_in[6];
    const float* Wn2 = (const float*)d_in[7];
    const float* bn2 = (const float*)d_in[8];
    float* out = (float*)d_out;

    pre_kernel<<<(Bc * Pc) / 8, 128>>>(h, We1, be1);
    dist_kernel<<<Bc * 32, 256>>>(h);
    edge_kernel<<<Bc * 64, 128>>>(We1);
    post_kernel<<<(Bc * Pc) / 8, 128>>>(h, We2, be2, Wn1, bn1, Wn2, bn2, out);
}

// round 2
// speedup vs baseline: 1.0853x; 1.0853x over previous
#include <cuda_runtime.h>

#define Bc 8
#define Pc 512
#define Dc 16
#define Ec 64
#define Hc 128

typedef unsigned long long u64;

// Scratch (no allocations allowed -> __device__ globals)
__device__ float g_a[Bc * Pc * Hc];     // a_s = ns @ We1[17:33]          (2 MB)
__device__ float g_c[Bc * Pc * Hc];     // c_r = nr @ We1[1:17] + be1     (2 MB)
__device__ float g_dist[Bc * Pc * Pc];  // dist[b][r][s]                  (8 MB)
__device__ float g_hsum[Bc * Pc * Hc];  // sum_s relu(hidden)             (2 MB)

// ---------------- packed f32x2 helpers (sm_103a) ----------------
__device__ __forceinline__ u64 add2(u64 a, u64 b) {
    u64 r; asm("add.rn.f32x2 %0,%1,%2;" : "=l"(r) : "l"(a), "l"(b)); return r;
}
__device__ __forceinline__ u64 fma2(u64 a, u64 b, u64 c) {
    u64 r; asm("fma.rn.f32x2 %0,%1,%2,%3;" : "=l"(r) : "l"(a), "l"(b), "l"(c)); return r;
}
__device__ __forceinline__ u64 pack2(float lo, float hi) {
    u64 r; asm("mov.b64 %0,{%1,%2};" : "=l"(r) : "f"(lo), "f"(hi)); return r;
}
__device__ __forceinline__ void unpack2(u64 x, float& lo, float& hi) {
    asm("mov.b64 {%0,%1},%2;" : "=f"(lo), "=f"(hi) : "l"(x));
}
__device__ __forceinline__ u64 relu2(u64 x) {
    float lo, hi; unpack2(x, lo, hi);
    return pack2(fmaxf(lo, 0.f), fmaxf(hi, 0.f));
}

// ---------------------------------------------------------------------------
// K1: per-node precompute a, c.  8 nodes per block, 128 threads (thread = k).
// ---------------------------------------------------------------------------
__global__ void pre_kernel(const float* __restrict__ h,
                           const float* __restrict__ We1,
                           const float* __restrict__ be1) {
    int node0 = blockIdx.x * 8;
    int k = threadIdx.x;

    __shared__ float nd[8][Dc];
    nd[k >> 4][k & 15] = h[node0 * Dc + k];
    __syncthreads();

    float a[8], c[8];
    float b1 = be1[k];
#pragma unroll
    for (int n = 0; n < 8; n++) { a[n] = 0.f; c[n] = b1; }

#pragma unroll
    for (int d = 0; d < Dc; d++) {
        float ws = We1[(17 + d) * Hc + k];
        float wr = We1[(1 + d) * Hc + k];
#pragma unroll
        for (int n = 0; n < 8; n++) {
            float x = nd[n][d];
            a[n] = fmaf(x, ws, a[n]);
            c[n] = fmaf(x, wr, c[n]);
        }
    }
#pragma unroll
    for (int n = 0; n < 8; n++) {
        g_a[(node0 + n) * Hc + k] = a[n];
        g_c[(node0 + n) * Hc + k] = c[n];
    }
}

// ---------------------------------------------------------------------------
// K2: pairwise distance matrix dist[b][r][s].
// ---------------------------------------------------------------------------
__global__ void dist_kernel(const float* __restrict__ h) {
    int b = blockIdx.x >> 5;
    int rc = blockIdx.x & 31;
    __shared__ float nd[Pc][Dc + 1];

    for (int i = threadIdx.x; i < Pc * Dc; i += blockDim.x)
        nd[i >> 4][i & 15] = h[b * Pc * Dc + i];
    __syncthreads();

    for (int idx = threadIdx.x; idx < 16 * Pc; idx += blockDim.x) {
        int r = rc * 16 + (idx >> 9);
        int s = idx & (Pc - 1);
        float acc = 0.f;
#pragma unroll
        for (int d = 0; d < Dc; d++) {
            float df = nd[r][d] - nd[s][d];
            acc = fmaf(df, df, acc);
        }
        g_dist[(b * Pc + r) * Pc + s] = sqrtf(acc);
    }
}

// ---------------------------------------------------------------------------
// K3: edge accumulation with packed f32x2.
// Block = 64 threads (thread = k-pair), 8 receivers. Grid = 8*64 = 512.
// hsum[r][k] = sum_{s != r} relu(dist*w0[k] + a_s[k] + c_r[k])
// ---------------------------------------------------------------------------
__global__ void edge_kernel(const float* __restrict__ We1) {
    int b = blockIdx.x >> 6;
    int r0 = (blockIdx.x & 63) * 8;
    int t = threadIdx.x;          // 0..63
    int k0 = t * 2;

    u64 w02 = *(const u64*)(We1 + k0);   // row 0 = dist weights (pair)

    const float* cbase = g_c + (b * Pc + r0) * Hc;
    u64 cr2[8], acc2[8];
#pragma unroll
    for (int n = 0; n < 8; n++) {
        cr2[n] = *(const u64*)(cbase + n * Hc + k0);
        acc2[n] = 0ull;  // bits of {0.f, 0.f}
    }

    __shared__ u64 sd2[8][64];   // duplicated {d,d} pairs
    const float* arow = g_a + b * Pc * Hc + k0;
    const float* drow = g_dist + (size_t)(b * Pc + r0) * Pc;

    for (int st = 0; st < Pc; st += 64) {
        __syncthreads();
#pragma unroll
        for (int i = 0; i < 8; i++) {
            float d = drow[i * Pc + st + t];
            sd2[i][t] = pack2(d, d);
        }
        __syncthreads();

#pragma unroll 4
        for (int ss = 0; ss < 64; ss++) {
            u64 av2 = *(const u64*)(arow + (st + ss) * Hc);
#pragma unroll
            for (int n = 0; n < 8; n++) {
                u64 t2  = add2(av2, cr2[n]);
                u64 pre = fma2(sd2[n][ss], w02, t2);
                acc2[n] = add2(acc2[n], relu2(pre));
            }
        }
    }

    // remove the s == r contribution exactly (dist(r,r) == 0), scalar epilogue
#pragma unroll
    for (int n = 0; n < 8; n++) {
        float clo, chi, alo, ahi, lo, hi;
        unpack2(cr2[n], clo, chi);
        alo = arow[(r0 + n) * Hc];
        ahi = arow[(r0 + n) * Hc + 1];
        unpack2(acc2[n], lo, hi);
        lo -= fmaxf(alo + clo, 0.f);
        hi -= fmaxf(ahi + chi, 0.f);
        float* dst = g_hsum + (b * Pc + r0 + n) * Hc + k0;
        dst[0] = lo;
        dst[1] = hi;
    }
}

// ---------------------------------------------------------------------------
// K4: agg = hsum @ We2 + 511*be2 ; node MLP.  8 nodes/block, 128 threads.
// Register-blocked with LDS.128 activations everywhere.
// ---------------------------------------------------------------------------
__global__ void post_kernel(const float* __restrict__ h,
                            const float* __restrict__ We2,
                            const float* __restrict__ be2,
                            const float* __restrict__ Wn1,
                            const float* __restrict__ bn1,
                            const float* __restrict__ Wn2,
                            const float* __restrict__ bn2,
                            float* __restrict__ out) {
    int node0 = blockIdx.x * 8;
    int t = threadIdx.x;

    __shared__ __align__(16) float Hs[8][Hc];        // 4 KB
    __shared__ __align__(16) float nin[8][Ec + Dc];  // 2.5 KB
    __shared__ __align__(16) float hid[8][Hc];       // 4 KB

    {   // load hsum: 1024 floats = 256 float4, 2 per thread
        const float4* src = (const float4*)(g_hsum + node0 * Hc);
        ((float4*)Hs)[t]       = src[t];
        ((float4*)Hs)[t + 128] = src[t + 128];
        // node features into nin[:, 64:80]
        nin[t >> 4][Ec + (t & 15)] = h[node0 * Dc + t];
    }
    __syncthreads();

    // Phase A: agg. j = t&63, 4 nodes register-blocked per thread.
    {
        int j = t & 63, half = t >> 6;
        float b2 = 511.0f * be2[j];
        float acc0 = b2, acc1 = b2, acc2_ = b2, acc3 = b2;
#pragma unroll 8
        for (int kk = 0; kk < Hc; kk += 4) {
            float w0 = We2[(kk + 0) * Ec + j];
            float w1 = We2[(kk + 1) * Ec + j];
            float w2 = We2[(kk + 2) * Ec + j];
            float w3 = We2[(kk + 3) * Ec + j];
            const float4* hr = (const float4*)(&Hs[half * 4][0]) + (kk >> 2);
            float4 v0 = hr[0];
            float4 v1 = hr[Hc / 4];
            float4 v2 = hr[2 * Hc / 4];
            float4 v3 = hr[3 * Hc / 4];
            acc0 = fmaf(v0.x, w0, acc0); acc0 = fmaf(v0.y, w1, acc0);
            acc0 = fmaf(v0.z, w2, acc0); acc0 = fmaf(v0.w, w3, acc0);
            acc1 = fmaf(v1.x, w0, acc1); acc1 = fmaf(v1.y, w1, acc1);
            acc1 = fmaf(v1.z, w2, acc1); acc1 = fmaf(v1.w, w3, acc1);
            acc2_ = fmaf(v2.x, w0, acc2_); acc2_ = fmaf(v2.y, w1, acc2_);
            acc2_ = fmaf(v2.z, w2, acc2_); acc2_ = fmaf(v2.w, w3, acc2_);
            acc3 = fmaf(v3.x, w0, acc3); acc3 = fmaf(v3.y, w1, acc3);
            acc3 = fmaf(v3.z, w2, acc3); acc3 = fmaf(v3.w, w3, acc3);
        }
        nin[half * 4 + 0][j] = acc0;
        nin[half * 4 + 1][j] = acc1;
        nin[half * 4 + 2][j] = acc2_;
        nin[half * 4 + 3][j] = acc3;
    }
    __syncthreads();

    // Phase B: hidden layer. thread = hidden unit, 8 nodes register-blocked.
    {
        float accs[8];
        float b1 = bn1[t];
#pragma unroll
        for (int n = 0; n < 8; n++) accs[n] = b1;
#pragma unroll 5
        for (int i = 0; i < Ec + Dc; i += 4) {
            float w0 = Wn1[(i + 0) * Hc + t];
            float w1 = Wn1[(i + 1) * Hc + t];
            float w2 = Wn1[(i + 2) * Hc + t];
            float w3 = Wn1[(i + 3) * Hc + t];
#pragma unroll
            for (int n = 0; n < 8; n++) {
                float4 v = *((const float4*)(&nin[n][0]) + (i >> 2));
                accs[n] = fmaf(v.x, w0, accs[n]);
                accs[n] = fmaf(v.y, w1, accs[n]);
                accs[n] = fmaf(v.z, w2, accs[n]);
                accs[n] = fmaf(v.w, w3, accs[n]);
            }
        }
#pragma unroll
        for (int n = 0; n < 8; n++)
            hid[n][t] = fmaxf(accs[n], 0.f);
    }
    __syncthreads();

    // Phase C: output layer. thread = (node, dim), 4 partial accumulators.
    {
        int n = t >> 4, d = t & 15;
        float a0 = 0.f, a1 = 0.f, a2 = 0.f, a3 = 0.f;
#pragma unroll 8
        for (int kk = 0; kk < Hc; kk += 4) {
            float4 v = *((const float4*)(&hid[n][0]) + (kk >> 2));
            a0 = fmaf(v.x, Wn2[(kk + 0) * Dc + d], a0);
            a1 = fmaf(v.y, Wn2[(kk + 1) * Dc + d], a1);
            a2 = fmaf(v.z, Wn2[(kk + 2) * Dc + d], a2);
            a3 = fmaf(v.w, Wn2[(kk + 3) * Dc + d], a3);
        }
        out[node0 * Dc + t] = bn2[d] + ((a0 + a1) + (a2 + a3));
    }
}

// ---------------------------------------------------------------------------
extern "C" void kernel_launch(void* const* d_in, const int* in_sizes, int n_in,
                              void* d_out, int out_size) {
    const float* h   = (const float*)d_in[0];
    const float* We1 = (const float*)d_in[1];
    const float* be1 = (const float*)d_in[2];
    const float* We2 = (const float*)d_in[3];
    const float* be2 = (const float*)d_in[4];
    const float* Wn1 = (const float*)d_in[5];
    const float* bn1 = (const float*)d_in[6];
    const float* Wn2 = (const float*)d_in[7];
    const float* bn2 = (const float*)d_in[8];
    float* out = (float*)d_out;

    pre_kernel<<<(Bc * Pc) / 8, 128>>>(h, We1, be1);
    dist_kernel<<<Bc * 32, 256>>>(h);
    edge_kernel<<<Bc * 64, 64>>>(We1);
    post_kernel<<<(Bc * Pc) / 8, 128>>>(h, We2, be2, Wn1, bn1, Wn2, bn2, out);
}

// round 3
// speedup vs baseline: 1.3767x; 1.2685x over previous
#include <cuda_runtime.h>

#define Bc 8
#define Pc 512
#define Dc 16
#define Ec 64
#define Hc 128

typedef unsigned long long u64;

// Scratch (no allocations allowed -> __device__ globals)
__device__ float g_a[Bc * Pc * Hc];     // a_s = ns @ We1[17:33]          (2 MB)
__device__ float g_c[Bc * Pc * Hc];     // c_r = nr @ We1[1:17] + be1     (2 MB)
__device__ float g_dist[Bc * Pc * Pc];  // dist[b][r][s]                  (8 MB)

// ---------------- packed f32x2 helpers (sm_103a) ----------------
__device__ __forceinline__ u64 add2(u64 a, u64 b) {
    u64 r; asm("add.rn.f32x2 %0,%1,%2;" : "=l"(r) : "l"(a), "l"(b)); return r;
}
__device__ __forceinline__ u64 fma2(u64 a, u64 b, u64 c) {
    u64 r; asm("fma.rn.f32x2 %0,%1,%2,%3;" : "=l"(r) : "l"(a), "l"(b), "l"(c)); return r;
}
__device__ __forceinline__ u64 pack2(float lo, float hi) {
    u64 r; asm("mov.b64 %0,{%1,%2};" : "=l"(r) : "f"(lo), "f"(hi)); return r;
}
__device__ __forceinline__ void unpack2(u64 x, float& lo, float& hi) {
    asm("mov.b64 {%0,%1},%2;" : "=f"(lo), "=f"(hi) : "l"(x));
}
__device__ __forceinline__ u64 relu2(u64 x) {
    float lo, hi; unpack2(x, lo, hi);
    return pack2(fmaxf(lo, 0.f), fmaxf(hi, 0.f));
}

// ---------------------------------------------------------------------------
// K1: per-node precompute a, c.  8 nodes per block, 128 threads (thread = k).
// ---------------------------------------------------------------------------
__global__ void pre_kernel(const float* __restrict__ h,
                           const float* __restrict__ We1,
                           const float* __restrict__ be1) {
    int node0 = blockIdx.x * 8;
    int k = threadIdx.x;

    __shared__ float nd[8][Dc];
    nd[k >> 4][k & 15] = h[node0 * Dc + k];
    __syncthreads();

    float a[8], c[8];
    float b1 = be1[k];
#pragma unroll
    for (int n = 0; n < 8; n++) { a[n] = 0.f; c[n] = b1; }

#pragma unroll
    for (int d = 0; d < Dc; d++) {
        float ws = We1[(17 + d) * Hc + k];
        float wr = We1[(1 + d) * Hc + k];
#pragma unroll
        for (int n = 0; n < 8; n++) {
            float x = nd[n][d];
            a[n] = fmaf(x, ws, a[n]);
            c[n] = fmaf(x, wr, c[n]);
        }
    }
#pragma unroll
    for (int n = 0; n < 8; n++) {
        g_a[(node0 + n) * Hc + k] = a[n];
        g_c[(node0 + n) * Hc + k] = c[n];
    }
}

// ---------------------------------------------------------------------------
// K2: pairwise distance matrix dist[b][r][s].
// ---------------------------------------------------------------------------
__global__ void dist_kernel(const float* __restrict__ h) {
    int b = blockIdx.x >> 5;
    int rc = blockIdx.x & 31;
    __shared__ float nd[Pc][Dc + 1];

    for (int i = threadIdx.x; i < Pc * Dc; i += blockDim.x)
        nd[i >> 4][i & 15] = h[b * Pc * Dc + i];
    __syncthreads();

    for (int idx = threadIdx.x; idx < 16 * Pc; idx += blockDim.x) {
        int r = rc * 16 + (idx >> 9);
        int s = idx & (Pc - 1);
        float acc = 0.f;
#pragma unroll
        for (int d = 0; d < Dc; d++) {
            float df = nd[r][d] - nd[s][d];
            acc = fmaf(df, df, acc);
        }
        g_dist[(b * Pc + r) * Pc + s] = sqrtf(acc);
    }
}

// ---------------------------------------------------------------------------
// K3 (fused): edge accumulation + agg-GEMM + node MLP.
// Grid = 512 blocks (b, 8 receivers), 256 threads = (sender-quarter q, k-pair tk).
// Main loop: acc2[8 recv] partial sums over this quarter's 128 senders.
// Epilogue: cross-quarter reduce in smem, exact self-term removal, then the
// whole post-MLP runs in-block on the resident hsum.
// ---------------------------------------------------------------------------
__global__ void __launch_bounds__(256, 1)
edgepost_kernel(const float* __restrict__ h,
                const float* __restrict__ We1,
                const float* __restrict__ We2,
                const float* __restrict__ be2,
                const float* __restrict__ Wn1,
                const float* __restrict__ bn1,
                const float* __restrict__ Wn2,
                const float* __restrict__ bn2,
                float* __restrict__ out) {
    int b = blockIdx.x >> 6;
    int r0 = (blockIdx.x & 63) * 8;
    int node0 = b * Pc + r0;            // global node index of receiver 0
    int t = threadIdx.x;
    int tk = t & 63;                    // k-pair id (k = 2*tk, 2*tk+1)
    int q  = t >> 6;                    // sender quarter 0..3
    int k0 = tk * 2;

    __shared__ u64 sbuf[8][4][64];                    // dist tiles, then partials (16 KB)
    __shared__ __align__(16) float Hs[8][Hc];         // hsum (4 KB)
    __shared__ __align__(16) float nin[8][Ec + Dc];   // [agg | node feats]
    __shared__ __align__(16) float hid[8][Hc];

    u64 w02 = *(const u64*)(We1 + k0);  // row 0 = dist weights (pair)

    const float* cbase = g_c + node0 * Hc;
    u64 cr2[8], acc2[8];
#pragma unroll
    for (int n = 0; n < 8; n++) {
        cr2[n] = *(const u64*)(cbase + n * Hc + k0);
        acc2[n] = 0ull;
    }

    const float* arow = g_a + (b * Pc + q * 128) * Hc + k0;
    const float* drow = g_dist + (size_t)node0 * Pc + q * 128;

    // ---- main loop: this quarter's 128 senders in two 64-wide stages ----
#pragma unroll
    for (int st = 0; st < 128; st += 64) {
        __syncthreads();
#pragma unroll
        for (int i = 0; i < 8; i++) {
            float d = drow[i * Pc + st + tk];
            sbuf[i][q][tk] = pack2(d, d);
        }
        __syncthreads();

#pragma unroll 4
        for (int ss = 0; ss < 64; ss++) {
            u64 av2 = *(const u64*)(arow + (st + ss) * Hc);
#pragma unroll
            for (int n = 0; n < 8; n++) {
                u64 t2  = add2(av2, cr2[n]);
                u64 pre = fma2(sbuf[n][q][ss], w02, t2);
                acc2[n] = add2(acc2[n], relu2(pre));
            }
        }
    }

    // ---- cross-quarter reduction + exact self-term removal ----
    __syncthreads();
#pragma unroll
    for (int n = 0; n < 8; n++)
        sbuf[n][q][tk] = acc2[n];
    __syncthreads();

#pragma unroll
    for (int g = 0; g < 2; g++) {
        int n = q + g * 4;
        u64 s = add2(add2(sbuf[n][0][tk], sbuf[n][1][tk]),
                     add2(sbuf[n][2][tk], sbuf[n][3][tk]));
        float lo, hi; unpack2(s, lo, hi);
        // remove s == r contribution: dist(r,r)==0 -> relu(a_r + c_r), exact
        float al = g_a[(node0 + n) * Hc + k0];
        float ah = g_a[(node0 + n) * Hc + k0 + 1];
        float cl = g_c[(node0 + n) * Hc + k0];
        float ch = g_c[(node0 + n) * Hc + k0 + 1];
        Hs[n][k0]     = lo - fmaxf(al + cl, 0.f);
        Hs[n][k0 + 1] = hi - fmaxf(ah + ch, 0.f);
    }
    // node features into nin[:, 64:80]
    if (t < 128)
        nin[t >> 4][Ec + (t & 15)] = h[node0 * Dc + t];
    __syncthreads();

    // ---- Phase A: agg = hsum @ We2 + 511*be2.  thread = (j, node-pair) ----
    {
        int j = tk;                 // 0..63
        int n0 = q * 2, n1 = n0 + 1;
        float b2 = 511.0f * be2[j];
        float a0 = b2, a1 = b2;
#pragma unroll 8
        for (int kk = 0; kk < Hc; kk += 4) {
            float w0 = We2[(kk + 0) * Ec + j];
            float w1 = We2[(kk + 1) * Ec + j];
            float w2 = We2[(kk + 2) * Ec + j];
            float w3 = We2[(kk + 3) * Ec + j];
            float4 v0 = *((const float4*)&Hs[n0][0] + (kk >> 2));
            float4 v1 = *((const float4*)&Hs[n1][0] + (kk >> 2));
            a0 = fmaf(v0.x, w0, a0); a0 = fmaf(v0.y, w1, a0);
            a0 = fmaf(v0.z, w2, a0); a0 = fmaf(v0.w, w3, a0);
            a1 = fmaf(v1.x, w0, a1); a1 = fmaf(v1.y, w1, a1);
            a1 = fmaf(v1.z, w2, a1); a1 = fmaf(v1.w, w3, a1);
        }
        nin[n0][j] = a0;
        nin[n1][j] = a1;
    }
    __syncthreads();

    // ---- Phase B: hidden layer. thread = (hidden unit, node-half) ----
    {
        int hu = t & 127, g = t >> 7;   // g = 0/1 -> nodes g*4..g*4+3
        float b1 = bn1[hu];
        float accs[4];
#pragma unroll
        for (int m = 0; m < 4; m++) accs[m] = b1;
#pragma unroll 5
        for (int i = 0; i < Ec + Dc; i += 4) {
            float w0 = Wn1[(i + 0) * Hc + hu];
            float w1 = Wn1[(i + 1) * Hc + hu];
            float w2 = Wn1[(i + 2) * Hc + hu];
            float w3 = Wn1[(i + 3) * Hc + hu];
#pragma unroll
            for (int m = 0; m < 4; m++) {
                float4 v = *((const float4*)&nin[g * 4 + m][0] + (i >> 2));
                accs[m] = fmaf(v.x, w0, accs[m]);
                accs[m] = fmaf(v.y, w1, accs[m]);
                accs[m] = fmaf(v.z, w2, accs[m]);
                accs[m] = fmaf(v.w, w3, accs[m]);
            }
        }
#pragma unroll
        for (int m = 0; m < 4; m++)
            hid[g * 4 + m][hu] = fmaxf(accs[m], 0.f);
    }
    __syncthreads();

    // ---- Phase C: output layer. 128 threads = (node, dim) ----
    if (t < 128) {
        int n = t >> 4, d = t & 15;
        float a0 = 0.f, a1 = 0.f, a2 = 0.f, a3 = 0.f;
#pragma unroll 8
        for (int kk = 0; kk < Hc; kk += 4) {
            float4 v = *((const float4*)&hid[n][0] + (kk >> 2));
            a0 = fmaf(v.x, Wn2[(kk + 0) * Dc + d], a0);
            a1 = fmaf(v.y, Wn2[(kk + 1) * Dc + d], a1);
            a2 = fmaf(v.z, Wn2[(kk + 2) * Dc + d], a2);
            a3 = fmaf(v.w, Wn2[(kk + 3) * Dc + d], a3);
        }
        out[node0 * Dc + t] = bn2[d] + ((a0 + a1) + (a2 + a3));
    }
}

// ---------------------------------------------------------------------------
extern "C" void kernel_launch(void* const* d_in, const int* in_sizes, int n_in,
                              void* d_out, int out_size) {
    const float* h   = (const float*)d_in[0];
    const float* We1 = (const float*)d_in[1];
    const float* be1 = (const float*)d_in[2];
    const float* We2 = (const float*)d_in[3];
    const float* be2 = (const float*)d_in[4];
    const float* Wn1 = (const float*)d_in[5];
    const float* bn1 = (const float*)d_in[6];
    const float* Wn2 = (const float*)d_in[7];
    const float* bn2 = (const float*)d_in[8];
    float* out = (float*)d_out;

    pre_kernel<<<(Bc * Pc) / 8, 128>>>(h, We1, be1);
    dist_kernel<<<Bc * 32, 256>>>(h);
    edgepost_kernel<<<Bc * 64, 256>>>(h, We1, We2, be2, Wn1, bn1, Wn2, bn2, out);
}